// round 5
// baseline (speedup 1.0000x reference)
#include <cuda_runtime.h>
#include <cuda_fp16.h>
#include <math.h>

// ============================================================================
// PermInvariantQNN — exact piecewise-linear collapse of the scalar encoder.
// Round 5: hybrid bitonic + balanced cell build, 4-block record kernel,
//          clean/dirty cell encoding (skip bp probe), f32x2 packed decoder.
// ============================================================================

#define BATCH     131072
#define NBP_MAX   512
#define NSEG_MAX  512
#define NCELL     4096
#define XLO_F     (-6.0f)
#define STEP_F    (12.0f / 4096.0f)
#define INVSTEP_F (4096.0f / 12.0f)
#define HALFCELLS 2048.0f

__device__ float          g_bp[NBP_MAX];        // sorted breakpoints, +INF padded
__device__ unsigned int   g_rec[NSEG_MAX * 6];  // [xmid f32, 5x half2(s,v)] * (1/64)
__device__ int            g_nbp;
__device__ unsigned short g_cell[NCELL];        // low15: lo_c, bit15: dirty
__device__ float          g_mom[5 * BATCH];     // SoA moments scratch

// ---------------------------------------------------------------------------
// f32x2 packed helpers (Blackwell FFMA2 via PTX)
// ---------------------------------------------------------------------------
typedef unsigned long long u64;
__device__ __forceinline__ u64 pk2(float a, float b) {
    u64 r; asm("mov.b64 %0, {%1, %2};" : "=l"(r) : "f"(a), "f"(b)); return r;
}
__device__ __forceinline__ float2 up2(u64 v) {
    float2 f; asm("mov.b64 {%0, %1}, %2;" : "=f"(f.x), "=f"(f.y) : "l"(v)); return f;
}
__device__ __forceinline__ u64 ffma2(u64 a, u64 b, u64 c) {
    u64 d; asm("fma.rn.f32x2 %0, %1, %2, %3;" : "=l"(d) : "l"(a), "l"(b), "l"(c)); return d;
}
__device__ __forceinline__ u64 relu2(u64 v) {
    float2 f = up2(v);
    return pk2(fmaxf(f.x, 0.0f), fmaxf(f.y, 0.0f));
}

// ----------------------------------------------------------------------------
// Prep A: sort + cell table. 1 block x 512 threads.
// ----------------------------------------------------------------------------
__global__ void prep_sort_kernel(const float* __restrict__ eW1, const float* __restrict__ eb1,
                                 const float* __restrict__ eW2, const float* __restrict__ eb2)
{
    __shared__ float sa[20], sb1[20], sW2[400], sb2[20];
    __shared__ float s_t[21];
    __shared__ int   s_n1, s_n;
    __shared__ float cand[512];
    __shared__ unsigned short s_lo[NCELL];

    const int tid = threadIdx.x;

    if (tid < 20)  { sa[tid] = eW1[tid]; sb1[tid] = eb1[tid]; sb2[tid] = eb2[tid]; }
    if (tid < 400) sW2[tid] = eW2[tid];
    cand[tid] = INFINITY;
    if (tid == 0) s_n = 0;
    __syncthreads();

    // phase 1: layer-1 breakpoints via warp rank-sort
    if (tid < 32) {
        float tj = INFINITY;
        if (tid < 20) {
            float a = sa[tid];
            if (a != 0.0f) {
                float t = -sb1[tid] / a;
                if (isfinite(t)) tj = t;
            }
        }
        int rnk = 0;
        #pragma unroll
        for (int j = 0; j < 32; j++) {
            float u = __shfl_sync(0xFFFFFFFFu, tj, j);
            rnk += (u < tj) || (u == tj && j < tid);
        }
        bool fin = isfinite(tj);
        if (fin) { s_t[rnk] = tj; cand[rnk] = tj; }
        unsigned m = __ballot_sync(0xFFFFFFFFu, fin);
        if (tid == 0) { s_n1 = __popc(m); atomicAdd(&s_n, __popc(m)); }
    }
    __syncthreads();
    const int n1 = s_n1;

    // phase 2: layer-2 zero crossings
    if (tid < 21 * 20) {
        int p = tid / 20, k = tid % 20;
        if (p <= n1) {
            float lo = (p == 0)  ? -INFINITY : s_t[p - 1];
            float hi = (p == n1) ?  INFINITY : s_t[p];
            float xr;
            if (n1 == 0)      xr = 0.0f;
            else if (p == 0)  xr = s_t[0] - 1.0f;
            else if (p == n1) xr = s_t[n1 - 1] + 1.0f;
            else              xr = 0.5f * (lo + hi);
            float zs = 0.0f, zi = sb2[k];
            for (int j = 0; j < 20; j++) {
                float pre = fmaf(sa[j], xr, sb1[j]);
                if (pre > 0.0f) {
                    zs = fmaf(sa[j],  sW2[j * 20 + k], zs);
                    zi = fmaf(sb1[j], sW2[j * 20 + k], zi);
                }
            }
            if (zs != 0.0f) {
                float xc = -zi / zs;
                if (isfinite(xc) && xc > lo && xc < hi) {
                    cand[20 + p * 20 + k] = xc;
                    atomicAdd(&s_n, 1);
                }
            }
        }
    }
    __syncthreads();

    // phase 3: hybrid bitonic sort (intra-warp stages via shfl)
    {
        float v = cand[tid];
        for (int k = 2; k <= 512; k <<= 1) {
            for (int j = k >> 1; j > 0; j >>= 1) {
                float u;
                if (j >= 32) {
                    cand[tid] = v; __syncthreads();
                    u = cand[tid ^ j]; __syncthreads();
                } else {
                    u = __shfl_xor_sync(0xFFFFFFFFu, v, j);
                }
                bool up = ((tid & k) == 0);
                bool keepmin = (up == ((tid & j) == 0));
                v = keepmin ? fminf(v, u) : fmaxf(v, u);
            }
        }
        cand[tid] = v;
        __syncthreads();
    }

    const int n = s_n;
    if (tid == 0) g_nbp = n;
    g_bp[tid] = cand[tid];                       // +INF padded

    // phase 4: per-cell upper-bound (balanced) + dirty bits
    for (int c = tid; c < NCELL; c += 512) {
        float left = XLO_F + (float)c * STEP_F;
        int lo = 0, hi = 512;                    // INF padding makes 512-wide search safe
        while (lo < hi) {
            int mid = (lo + hi) >> 1;
            if (cand[mid] <= left) lo = mid + 1; else hi = mid;
        }
        s_lo[c] = (unsigned short)lo;
    }
    __syncthreads();
    for (int c = tid; c < NCELL; c += 512) {
        int lo = s_lo[c];
        int hi = (c == NCELL - 1) ? n : (int)s_lo[c + 1];
        g_cell[c] = (unsigned short)(lo | (hi > lo ? 0x8000 : 0));
    }
}

// ----------------------------------------------------------------------------
// Prep B: per-segment records. 4 blocks x 128 threads.
// ----------------------------------------------------------------------------
__global__ void prep_rec_kernel(const float* __restrict__ eW1, const float* __restrict__ eb1,
                                const float* __restrict__ eW2, const float* __restrict__ eb2,
                                const float* __restrict__ eW3, const float* __restrict__ eb3)
{
    __shared__ float sa[20], sb1[20], sW2[400], sb2[20], sW3[100], sb3[5];
    const int tid = threadIdx.x;
    if (tid < 20)  { sa[tid] = eW1[tid]; sb1[tid] = eb1[tid]; sb2[tid] = eb2[tid]; }
    for (int i = tid; i < 400; i += 128) sW2[i] = eW2[i];
    if (tid < 100) sW3[tid] = eW3[tid];
    if (tid < 5)   sb3[tid] = eb3[tid];
    __syncthreads();

    const int sid = blockIdx.x * 128 + tid;
    const int n   = g_nbp;
    if (sid > n) return;

    float xr;
    if (n == 0)        xr = 0.0f;
    else if (sid == 0) xr = g_bp[0] - 1.0f;
    else if (sid == n) xr = g_bp[n - 1] + 1.0f;
    else               xr = 0.5f * (g_bp[sid - 1] + g_bp[sid]);

    float ha[20], hb[20];
    #pragma unroll
    for (int j = 0; j < 20; j++) {
        float pre = fmaf(sa[j], xr, sb1[j]);
        bool act = pre > 0.0f;
        ha[j] = act ? sa[j]  : 0.0f;
        hb[j] = act ? sb1[j] : 0.0f;
    }
    float sm[5] = {0, 0, 0, 0, 0}, cm[5] = {0, 0, 0, 0, 0};
    for (int k = 0; k < 20; k++) {
        float zs = 0.0f, zi = sb2[k];
        #pragma unroll
        for (int j = 0; j < 20; j++) {
            zs = fmaf(ha[j], sW2[j * 20 + k], zs);
            zi = fmaf(hb[j], sW2[j * 20 + k], zi);
        }
        if (fmaf(zs, xr, zi) > 0.0f) {
            #pragma unroll
            for (int m = 0; m < 5; m++) {
                sm[m] = fmaf(zs, sW3[k * 5 + m], sm[m]);
                cm[m] = fmaf(zi, sW3[k * 5 + m], cm[m]);
            }
        }
    }
    unsigned int* rec = g_rec + sid * 6;
    rec[0] = __float_as_uint(xr);
    #pragma unroll
    for (int m = 0; m < 5; m++) {
        float v = fmaf(sm[m], xr, cm[m] + sb3[m]);   // f_m at xr
        __half2 h = __floats2half2_rn(sm[m] * 0.015625f, v * 0.015625f);
        rec[1 + m] = *(unsigned int*)&h;
    }
}

// ----------------------------------------------------------------------------
// Encoder kernel: 1 row/thread, clean/dirty cell lookup.
// ----------------------------------------------------------------------------
__device__ __forceinline__ int pwl_find(float x,
                                        const float* __restrict__ s_bp,
                                        const unsigned short* __restrict__ s_cell)
{
    float fc = fmaf(x, INVSTEP_F, HALFCELLS);
    int c = __float2int_rz(fc);
    c = min(max(c, 0), NCELL - 1);
    unsigned e = s_cell[c];
    int s = e & 0x7FFF;
    bool walk = (e & 0x8000u) != 0;
    if (fc < 0.0f) { s = 0; walk = true; }
    if (walk) { while (s_bp[s] <= x) ++s; }      // +INF padding terminates
    return s;
}

__device__ __forceinline__ void pwl_acc(float x, const uint2* __restrict__ p,
                                        float acc[5])
{
    uint2 r0 = p[0], r1 = p[1], r2 = p[2];
    float dx = x - __uint_as_float(r0.x);
    float2 m0 = __half22float2(*(__half2*)&r0.y);
    float2 m1 = __half22float2(*(__half2*)&r1.x);
    float2 m2 = __half22float2(*(__half2*)&r1.y);
    float2 m3 = __half22float2(*(__half2*)&r2.x);
    float2 m4 = __half22float2(*(__half2*)&r2.y);
    acc[0] += fmaf(m0.x, dx, m0.y);
    acc[1] += fmaf(m1.x, dx, m1.y);
    acc[2] += fmaf(m2.x, dx, m2.y);
    acc[3] += fmaf(m3.x, dx, m3.y);
    acc[4] += fmaf(m4.x, dx, m4.y);
}

__global__ __launch_bounds__(128, 9) void enc_kernel(const float* __restrict__ inv)
{
    __shared__ __align__(16) float          s_bp[NBP_MAX];       // 2 KB
    __shared__ __align__(16) unsigned int   s_rec[NSEG_MAX * 6]; // 12 KB
    __shared__ __align__(16) unsigned short s_cell[NCELL];       // 8 KB

    const int tid = threadIdx.x;

    {
        const uint4* src = (const uint4*)g_rec;
        uint4* dst = (uint4*)s_rec;
        #pragma unroll
        for (int i = tid; i < NSEG_MAX * 6 / 4; i += 128) dst[i] = src[i];
        ((float4*)s_bp)[tid] = ((const float4*)g_bp)[tid];
        const uint4* csrc = (const uint4*)g_cell;
        uint4* cdst = (uint4*)s_cell;
        #pragma unroll
        for (int i = tid; i < NCELL / 8; i += 128) cdst[i] = csrc[i];
    }
    __syncthreads();

    const int r = blockIdx.x * 128 + tid;
    const uint2* rec = (const uint2*)s_rec;

    float acc[5] = {0, 0, 0, 0, 0};
    const float4* p0 = (const float4*)inv + (size_t)r * 16;
    #pragma unroll 4
    for (int i = 0; i < 16; i++) {
        float4 a = p0[i];
        int sA = pwl_find(a.x, s_bp, s_cell);
        int sB = pwl_find(a.y, s_bp, s_cell);
        int sC = pwl_find(a.z, s_bp, s_cell);
        int sD = pwl_find(a.w, s_bp, s_cell);
        pwl_acc(a.x, rec + sA * 3, acc);
        pwl_acc(a.y, rec + sB * 3, acc);
        pwl_acc(a.z, rec + sC * 3, acc);
        pwl_acc(a.w, rec + sD * 3, acc);
    }

    #pragma unroll
    for (int m = 0; m < 5; m++) g_mom[m * BATCH + r] = acc[m];
}

// ----------------------------------------------------------------------------
// Decoder kernel: 2 rows/thread packed into f32x2 (FFMA2).
// ----------------------------------------------------------------------------
__global__ __launch_bounds__(128, 4) void dec_kernel(
    const float* __restrict__ noninv,
    const float* __restrict__ dW1,  const float* __restrict__ db1,
    const float* __restrict__ dW2,  const float* __restrict__ db2,
    const float* __restrict__ dW3,  const float* __restrict__ db3,
    float* __restrict__ out)
{
    __shared__ __align__(16) u64 s_pw[784]; // dW1[260] db1[20] dW2[400] db2[20] dW3[80] db3[4]
    const int tid = threadIdx.x;

    for (int i = tid; i < 260; i += 128) { float w = dW1[i]; s_pw[i] = pk2(w, w); }
    for (int i = tid; i < 400; i += 128) { float w = dW2[i]; s_pw[280 + i] = pk2(w, w); }
    if (tid < 20) { float w = db1[tid]; s_pw[260 + tid] = pk2(w, w); }
    if (tid < 20) { float w = db2[tid]; s_pw[680 + tid] = pk2(w, w); }
    if (tid < 80) { float w = dW3[tid]; s_pw[700 + tid] = pk2(w, w); }
    if (tid < 4)  { float w = db3[tid]; s_pw[780 + tid] = pk2(w, w); }
    __syncthreads();

    const int ra = blockIdx.x * 128 + tid;
    const int rb = ra + BATCH / 2;

    u64 cat[13];
    #pragma unroll
    for (int m = 0; m < 5; m++)
        cat[m] = pk2(g_mom[m * BATCH + ra], g_mom[m * BATCH + rb]);
    {
        float4 a0 = *(const float4*)(noninv + (size_t)ra * 8);
        float4 a1 = *(const float4*)(noninv + (size_t)ra * 8 + 4);
        float4 b0 = *(const float4*)(noninv + (size_t)rb * 8);
        float4 b1 = *(const float4*)(noninv + (size_t)rb * 8 + 4);
        cat[5]  = pk2(a0.x, b0.x); cat[6]  = pk2(a0.y, b0.y);
        cat[7]  = pk2(a0.z, b0.z); cat[8]  = pk2(a0.w, b0.w);
        cat[9]  = pk2(a1.x, b1.x); cat[10] = pk2(a1.y, b1.y);
        cat[11] = pk2(a1.z, b1.z); cat[12] = pk2(a1.w, b1.w);
    }

    u64 h[20];
    #pragma unroll
    for (int kg = 0; kg < 20; kg += 4) {
        u64 z0 = s_pw[260 + kg], z1 = s_pw[261 + kg], z2 = s_pw[262 + kg], z3 = s_pw[263 + kg];
        #pragma unroll
        for (int c = 0; c < 13; c++) {
            z0 = ffma2(cat[c], s_pw[c * 20 + kg],     z0);
            z1 = ffma2(cat[c], s_pw[c * 20 + kg + 1], z1);
            z2 = ffma2(cat[c], s_pw[c * 20 + kg + 2], z2);
            z3 = ffma2(cat[c], s_pw[c * 20 + kg + 3], z3);
        }
        h[kg] = relu2(z0); h[kg + 1] = relu2(z1);
        h[kg + 2] = relu2(z2); h[kg + 3] = relu2(z3);
    }

    u64 g[20];
    #pragma unroll
    for (int kg = 0; kg < 20; kg += 4) {
        u64 z0 = s_pw[680 + kg], z1 = s_pw[681 + kg], z2 = s_pw[682 + kg], z3 = s_pw[683 + kg];
        #pragma unroll
        for (int j = 0; j < 20; j++) {
            z0 = ffma2(h[j], s_pw[280 + j * 20 + kg],     z0);
            z1 = ffma2(h[j], s_pw[280 + j * 20 + kg + 1], z1);
            z2 = ffma2(h[j], s_pw[280 + j * 20 + kg + 2], z2);
            z3 = ffma2(h[j], s_pw[280 + j * 20 + kg + 3], z3);
        }
        g[kg] = relu2(z0); g[kg + 1] = relu2(z1);
        g[kg + 2] = relu2(z2); g[kg + 3] = relu2(z3);
    }

    u64 o0 = s_pw[780], o1 = s_pw[781], o2 = s_pw[782], o3 = s_pw[783];
    #pragma unroll
    for (int k = 0; k < 20; k++) {
        o0 = ffma2(g[k], s_pw[700 + k * 4],     o0);
        o1 = ffma2(g[k], s_pw[700 + k * 4 + 1], o1);
        o2 = ffma2(g[k], s_pw[700 + k * 4 + 2], o2);
        o3 = ffma2(g[k], s_pw[700 + k * 4 + 3], o3);
    }
    float2 f0 = up2(o0), f1 = up2(o1), f2 = up2(o2), f3 = up2(o3);
    *(float4*)(out + (size_t)ra * 4) = make_float4(f0.x, f1.x, f2.x, f3.x);
    *(float4*)(out + (size_t)rb * 4) = make_float4(f0.y, f1.y, f2.y, f3.y);
}

// ----------------------------------------------------------------------------
extern "C" void kernel_launch(void* const* d_in, const int* in_sizes, int n_in,
                              void* d_out, int out_size)
{
    (void)in_sizes; (void)n_in; (void)out_size;
    const float* invar  = (const float*)d_in[0];
    const float* noninv = (const float*)d_in[1];
    const float* eW1 = (const float*)d_in[2];
    const float* eb1 = (const float*)d_in[3];
    const float* eW2 = (const float*)d_in[4];
    const float* eb2 = (const float*)d_in[5];
    const float* eW3 = (const float*)d_in[6];
    const float* eb3 = (const float*)d_in[7];
    const float* dW1 = (const float*)d_in[8];
    const float* db1 = (const float*)d_in[9];
    const float* dW2 = (const float*)d_in[10];
    const float* db2 = (const float*)d_in[11];
    const float* dW3 = (const float*)d_in[12];
    const float* db3 = (const float*)d_in[13];

    prep_sort_kernel<<<1, 512>>>(eW1, eb1, eW2, eb2);
    prep_rec_kernel<<<4, 128>>>(eW1, eb1, eW2, eb2, eW3, eb3);
    enc_kernel<<<BATCH / 128, 128>>>(invar);
    dec_kernel<<<BATCH / 256, 128>>>(noninv, dW1, db1, dW2, db2, dW3, db3,
                                     (float*)d_out);
}